// round 10
// baseline (speedup 1.0000x reference)
#include <cuda_runtime.h>

// ---------------- problem constants ----------------
#define GX 1504
#define GY 1504
#define GZ 40
#define MAXV 150000
#define MAXP 10
#define N_MAX 2097152

#define SLOTBITS 22
#define SLOTS (1 << SLOTBITS)
#define SLOTMASK (SLOTS - 1)
#define BIG 0x40000000u                // phase-1 low32 offset; vids always < BIG

#define KBITS 19
#define KSLOTS (1 << KBITS)            // kept-voxel table: 150K keys / 512K slots
#define KMASK (KSLOTS - 1)

// output layout: voxels | coors | num_points | voxel_num  (all as float32)
#define VOX_OFF  0
#define COOR_OFF 7500000
#define NP_OFF   7950000
#define VN_OFF   8100000

#define TPB    256
#define TILE   256                           // 1 point per thread, tile == block
#define NB_MAX (N_MAX / TILE)                // 8192
#define M0     161792                        // 632*256; E[distinct]≈161.5K >> 150K
#define HGRID  (M0 / TPB)                    // 632 <= 740 co-resident (5 CTAs/SM)
#define TGRID  888                           // tail: 6 CTAs/SM co-resident
#define VB     128                           // emit voxels per block

// ---------------- device scratch ----------------
// Packed entry: high32 = flat+1 (key), low32 = BIG+(N-i) then vid.
// Persists across graph replays: stale (key|vid) dominated by BIG-offset atomicMax.
__device__ unsigned long long g_slot[SLOTS];  // 32 MB
__device__ int g_pflat[N_MAX];                // fallback-only per-point slot
__device__ unsigned long long g_tile[NB_MAX]; // lookback: (state<<32)|count
__device__ int g_sat;
__device__ int g_cnt[MAXV];
__device__ int g_idx[MAXV * MAXP];
__device__ unsigned long long g_kept[KSLOTS]; // (flat+1)<<32 | vid ; 0 = empty
__device__ unsigned g_bar_arrive;
__device__ unsigned g_bar_gen;

__device__ __forceinline__ unsigned hash_flat(int flat) {
    return ((unsigned)flat * 2654435761u) >> (32 - SLOTBITS);
}
__device__ __forceinline__ unsigned hash_kept(int flat) {
    return ((unsigned)flat * 0x9E3779B9u) >> (32 - KBITS);
}

// sense-reversing global barrier; caller guarantees all nb blocks co-resident
__device__ __forceinline__ void gbar(unsigned nb) {
    __syncthreads();
    if (threadIdx.x == 0) {
        __threadfence();
        unsigned gen = *((volatile unsigned*)&g_bar_gen);
        if (atomicAdd(&g_bar_arrive, 1u) == nb - 1u) {
            g_bar_arrive = 0u;
            __threadfence();
            atomicAdd(&g_bar_gen, 1u);
        } else {
            while (*((volatile unsigned*)&g_bar_gen) == gen) __nanosleep(40);
        }
        __threadfence();
    }
    __syncthreads();
}

// XLA-exact binning: fp32 sub, then multiply by compile-time fp32 reciprocal.
__device__ __forceinline__ int bin3(float x, float y, float z, int* flat) {
    const float rx = 1.0f / 0.1f;    // == 10.0f exactly
    const float rz = 1.0f / 0.15f;   // 0x40D55555
    int cx = (int)floorf(__fmul_rn(__fadd_rn(x, 75.2f), rx));
    int cy = (int)floorf(__fmul_rn(__fadd_rn(y, 75.2f), rx));
    int cz = (int)floorf(__fmul_rn(__fadd_rn(z, 2.0f), rz));
    if (cx < 0 || cx >= GX || cy < 0 || cy >= GY || cz < 0 || cz >= GZ) return 0;
    *flat = (cz * GY + cy) * GX + cx;
    return 1;
}

// head claim: probe-claim-record in one random line
__device__ __forceinline__ unsigned claim_record(int flat, unsigned v) {
    unsigned tag = (unsigned)(flat + 1);
    unsigned long long ent = ((unsigned long long)tag << 32) | v;
    unsigned h = hash_flat(flat);
    volatile unsigned long long* vs = (volatile unsigned long long*)g_slot;
    for (;;) {
        unsigned long long cur = vs[h];
        if ((unsigned)(cur >> 32) == tag) {        // warm replays: single read
            atomicMax(&g_slot[h], ent);
            break;
        }
        if (cur == 0ULL) {
            unsigned long long old = atomicCAS(&g_slot[h], 0ULL, ent);
            if (old == 0ULL) break;
            if ((unsigned)(old >> 32) == tag) { atomicMax(&g_slot[h], ent); break; }
        }
        h = (h + 1) & SLOTMASK;
    }
    return h;
}

// fallback claim (tail): head vids are FINAL (head kernel completed) -> never
// clobber a lo32 < BIG entry with BIG+(N-i) (which would always win atomicMax).
__device__ __forceinline__ unsigned claim_fb(int flat, unsigned v) {
    unsigned tag = (unsigned)(flat + 1);
    unsigned long long ent = ((unsigned long long)tag << 32) | v;
    unsigned h = hash_flat(flat);
    volatile unsigned long long* vs = (volatile unsigned long long*)g_slot;
    for (;;) {
        unsigned long long cur = vs[h];
        if ((unsigned)(cur >> 32) == tag) {
            if ((unsigned)cur >= BIG) atomicMax(&g_slot[h], ent);
            break;
        }
        if (cur == 0ULL) {
            unsigned long long old = atomicCAS(&g_slot[h], 0ULL, ent);
            if (old == 0ULL) break;
            if ((unsigned)(old >> 32) == tag) {
                if ((unsigned)old >= BIG) atomicMax(&g_slot[h], ent);
                break;
            }
        }
        h = (h + 1) & SLOTMASK;
    }
    return h;
}

// ---------------- fused tile (1 pt/thread): flag + lookback + assign + slot ----
__device__ void fused_tile(int tile, int pf, int N, int hi, int last_tile,
                           float* __restrict__ out, bool build_kept) {
    __shared__ int s_warp[8];
    __shared__ int s_prefix;

    int i = tile * TILE + threadIdx.x;
    unsigned long long ee = (pf >= 0) ? g_slot[pf] : 0ULL;   // L1 fresh this launch
    int first = (pf >= 0 && (unsigned)ee == BIG + (unsigned)(N - i)) ? 1 : 0;

    int lane = threadIdx.x & 31, wid = threadIdx.x >> 5;
    int x = first;
#pragma unroll
    for (int o = 1; o < 32; o <<= 1) {
        int y = __shfl_up_sync(0xFFFFFFFFu, x, o);
        if (lane >= o) x += y;
    }
    if (lane == 31) s_warp[wid] = x;
    __syncthreads();
    if (wid == 0) {
        int w = (lane < 8) ? s_warp[lane] : 0;
#pragma unroll
        for (int o = 1; o < 8; o <<= 1) {
            int y = __shfl_up_sync(0xFFFFFFFFu, w, o);
            if (lane >= o) w += y;
        }
        if (lane < 8) s_warp[lane] = w;
    }
    __syncthreads();
    int total = s_warp[7];
    int texcl = x - first + (wid > 0 ? s_warp[wid - 1] : 0);

    if (threadIdx.x == 0)
        *((volatile unsigned long long*)&g_tile[tile]) = (1ULL << 32) | (unsigned)total;

    if (wid == 0) {
        int excl = 0;
        int look = tile - 1;
        while (look >= 0) {
            int idx = look - lane;
            unsigned long long p = (idx >= 0)
                ? *((volatile unsigned long long*)&g_tile[idx])
                : (2ULL << 32);
            int st = (int)(p >> 32);
            int val = (int)(p & 0xFFFFFFFFULL);
            unsigned bp = __ballot_sync(0xFFFFFFFFu, st == 2);
            unsigned bn = __ballot_sync(0xFFFFFFFFu, st == 0);
            if (bp) {
                int j = __ffs(bp) - 1;
                unsigned need = j ? ((1u << j) - 1u) : 0u;
                if ((bn & need) == 0) {
                    int c = (lane <= j) ? val : 0;
#pragma unroll
                    for (int o = 16; o > 0; o >>= 1) c += __shfl_down_sync(0xFFFFFFFFu, c, o);
                    excl += __shfl_sync(0xFFFFFFFFu, c, 0);
                    break;
                }
            } else if (bn == 0) {
                int c = val;
#pragma unroll
                for (int o = 16; o > 0; o >>= 1) c += __shfl_down_sync(0xFFFFFFFFu, c, o);
                excl += __shfl_sync(0xFFFFFFFFu, c, 0);
                look -= 32;
            }
        }
        if (lane == 0) {
            int tot = excl + total;
            *((volatile unsigned long long*)&g_tile[tile]) = (2ULL << 32) | (unsigned)tot;
            s_prefix = excl;
            if (tile == last_tile) {
                if (build_kept) {
                    if (tot >= MAXV || hi >= N) {    // saturated or head covers all
                        g_sat = 1;
                        out[VN_OFF] = (float)(tot < MAXV ? tot : MAXV);
                    }
                } else {
                    out[VN_OFF] = (float)(tot < MAXV ? tot : MAXV);
                }
            }
        }
    }
    __syncthreads();

    int vid = s_prefix + texcl;
    if (first) {
        unsigned tag = (unsigned)(ee >> 32);
        int flat = (int)tag - 1;
        *((volatile unsigned long long*)&g_slot[pf]) =
            ((unsigned long long)tag << 32) | (unsigned)vid;   // unblocks spinners
        if (vid < MAXV) {
            int cx = flat % GX;
            int r = flat / GX;
            int cy = r % GY;
            int cz = r / GY;
            out[COOR_OFF + (size_t)vid * 3 + 0] = (float)cz;
            out[COOR_OFF + (size_t)vid * 3 + 1] = (float)cy;
            out[COOR_OFF + (size_t)vid * 3 + 2] = (float)cx;
            if (build_kept) {
                unsigned long long ent = ((unsigned long long)tag << 32) | (unsigned)vid;
                unsigned h2 = hash_kept(flat);
                volatile unsigned long long* vk = (volatile unsigned long long*)g_kept;
                for (;;) {
                    unsigned long long cur = vk[h2];
                    if ((unsigned)(cur >> 32) == tag) break;   // stale == idempotent
                    if (cur == 0ULL) {
                        unsigned long long old = atomicCAS(&g_kept[h2], 0ULL, ent);
                        if (old == 0ULL || (unsigned)(old >> 32) == tag) break;
                    }
                    h2 = (h2 + 1) & KMASK;
                }
            }
        }
    }
    __threadfence();
    __syncthreads();

    if (pf >= 0) {
        int v;
        if (first) {
            v = vid;
        } else {
            unsigned lo32 = (unsigned)*((volatile unsigned long long*)&g_slot[pf]);
            while (lo32 >= BIG) {
                __nanosleep(60);
                lo32 = (unsigned)*((volatile unsigned long long*)&g_slot[pf]);
            }
            v = (int)lo32;
        }
        if (v < MAXV) {
            int sl = atomicAdd(&g_cnt[v], 1);
            if (sl < MAXP) g_idx[v * MAXP + sl] = i;
        }
    }
}

// ---------------- kernel 1: head — init + bin (register-carried slot) + tiles --
__global__ void __launch_bounds__(TPB, 5) vox_head(const float* __restrict__ pts,
                                                   int N, int Nh, int nb_head,
                                                   float* __restrict__ out) {
    int tid = blockIdx.x * TPB + threadIdx.x;
    int gsz = gridDim.x * TPB;

    for (int i = tid; i < NB_MAX; i += gsz) g_tile[i] = 0ULL;
    if (tid == 0) g_sat = 0;
    for (int i = tid; i < MAXV; i += gsz) g_cnt[i] = 0;

    int pf = -1;
    if (tid < Nh) {
        float x = pts[(size_t)tid * 5 + 0];
        float y = pts[(size_t)tid * 5 + 1];
        float z = pts[(size_t)tid * 5 + 2];
        int flat;
        if (bin3(x, y, z, &flat))
            pf = (int)claim_record(flat, BIG + (unsigned)(N - tid));
    }
    gbar(gridDim.x);

    if ((int)blockIdx.x < nb_head)
        fused_tile(blockIdx.x, pf, N, Nh, nb_head - 1, out, true);
}

// ---------------- kernel 2: tail — membership stream (+ in-kernel fallback) ----
#define TELEMS 4
__global__ void __launch_bounds__(TPB, 6) vox_tail(const float* __restrict__ pts,
                                                   int N, int Nh, int nb_head,
                                                   int nb_total,
                                                   float* __restrict__ out) {
    int sat = *((volatile int*)&g_sat);
    int tid = blockIdx.x * TPB + threadIdx.x;
    int gsz = gridDim.x * TPB;
    int lane = threadIdx.x & 31;
    int nwarp = gsz >> 5;
    int gw = tid >> 5;
    int nchunks = (N - Nh + 32 * TELEMS - 1) / (32 * TELEMS);

    for (int ch = gw; ch < nchunks; ch += nwarp) {
        int base = Nh + ch * (32 * TELEMS) + lane;
        float px[TELEMS], py[TELEMS], pz[TELEMS];
        int ok[TELEMS], flat[TELEMS];
#pragma unroll
        for (int k = 0; k < TELEMS; k++) {
            int i = base + k * 32;
            ok[k] = (i < N);
            if (ok[k]) {
                px[k] = __ldg(pts + (size_t)i * 5 + 0);
                py[k] = __ldg(pts + (size_t)i * 5 + 1);
                pz[k] = __ldg(pts + (size_t)i * 5 + 2);
            }
        }
#pragma unroll
        for (int k = 0; k < TELEMS; k++)
            if (ok[k]) ok[k] = bin3(px[k], py[k], pz[k], &flat[k]);

        if (sat) {
            unsigned h[TELEMS];
            unsigned long long e[TELEMS];
#pragma unroll
            for (int k = 0; k < TELEMS; k++) {
                if (ok[k]) {
                    h[k] = hash_kept(flat[k]);
                    e[k] = g_kept[h[k]];                  // batched first probes
                }
            }
#pragma unroll
            for (int k = 0; k < TELEMS; k++) {
                if (!ok[k]) continue;
                unsigned tag = (unsigned)(flat[k] + 1);
                unsigned hh = h[k];
                unsigned long long cur = e[k];
                for (;;) {
                    if (cur == 0ULL) break;               // voxel not kept
                    if ((unsigned)(cur >> 32) == tag) {
                        int v = (int)(unsigned)(cur & 0xFFFFFFFFULL);
                        int i = base + k * 32;
                        int sl = atomicAdd(&g_cnt[v], 1);
                        if (sl < MAXP) g_idx[v * MAXP + sl] = i;
                        break;
                    }
                    hh = (hh + 1) & KMASK;
                    cur = g_kept[hh];
                }
            }
        } else {
#pragma unroll
            for (int k = 0; k < TELEMS; k++) {
                int i = base + k * 32;
                if (i >= N) continue;
                if (!ok[k]) { g_pflat[i] = -1; continue; }
                g_pflat[i] = (int)claim_fb(flat[k], BIG + (unsigned)(N - i));
            }
        }
    }

    if (!sat) {
        // fallback: finish scan pipeline in-kernel. All TGRID blocks co-resident;
        // block-strided tiles -> lookback targets are concurrent or done.
        gbar(gridDim.x);
        for (int t = nb_head + (int)blockIdx.x; t < nb_total; t += (int)gridDim.x) {
            int i = t * TILE + threadIdx.x;
            int pf = (i < N) ? g_pflat[i] : -1;
            fused_tile(t, pf, N, N, nb_total - 1, out, false);
            __syncthreads();
        }
    }
}

// ---------------- kernel 3: emit — 2 threads/voxel, 25.6KB staging -------------
__global__ void __launch_bounds__(TPB) vox_emit(const float* __restrict__ pts,
                                                float* __restrict__ out) {
    __shared__ float srow[VB * 50];            // 25.6 KB -> 6 CTAs/SM
    int t = blockIdx.x;
    int vloc = threadIdx.x & (VB - 1);
    int half = threadIdx.x >> 7;               // 0: slots 0-4, 1: slots 5-9
    int vid = t * VB + vloc;
    if (vid < MAXV) {
        int c = g_cnt[vid];
        int m = c < MAXP ? c : MAXP;
        int a[MAXP];
        for (int k = 0; k < m; k++) a[k] = g_idx[vid * MAXP + k];
        for (int k = 1; k < m; k++) {          // restores deterministic point order
            int v = a[k];
            int j = k - 1;
            while (j >= 0 && a[j] > v) { a[j + 1] = a[j]; j--; }
            a[j + 1] = v;
        }
        float* row = srow + vloc * 50 + half * 25;
#pragma unroll
        for (int q = 0; q < 25; q++) row[q] = 0.0f;
        int k0 = half * 5;
        int k1 = m < k0 + 5 ? m : k0 + 5;
        for (int k = k0; k < k1; k++) {
            const float* p = pts + (size_t)a[k] * 5;
            float* d = row + (k - k0) * 5;
            d[0] = __ldg(p + 0);
            d[1] = __ldg(p + 1);
            d[2] = __ldg(p + 2);
            d[3] = __ldg(p + 3);
            d[4] = __ldg(p + 4);
        }
        if (half == 0) {
            out[NP_OFF + vid] = (float)m;
            if (m == 0) {                      // invalid slot -> coors = -1
                out[COOR_OFF + (size_t)vid * 3 + 0] = -1.0f;
                out[COOR_OFF + (size_t)vid * 3 + 1] = -1.0f;
                out[COOR_OFF + (size_t)vid * 3 + 2] = -1.0f;
            }
        }
    }
    __syncthreads();
    int rows = MAXV - t * VB;
    if (rows > VB) rows = VB;
    int nf4 = rows * 50 / 4;                   // 128->1600, 112->1400 (both exact)
    const float4* s4 = (const float4*)srow;
    float4* o4 = (float4*)(out + VOX_OFF + (size_t)t * VB * 50);
    for (int j = threadIdx.x; j < nf4; j += TPB) o4[j] = s4[j];
}

// ---------------- launch ----------------
extern "C" void kernel_launch(void* const* d_in, const int* in_sizes, int n_in,
                              void* d_out, int out_size) {
    const float* pts = (const float*)d_in[0];
    int N = in_sizes[0] / 5;
    if (N > N_MAX) N = N_MAX;
    float* out = (float*)d_out;

    int Nh = N < M0 ? N : M0;
    int nb_head = (Nh + TILE - 1) / TILE;      // <= 632
    int nb_total = (N + TILE - 1) / TILE;

    vox_head<<<HGRID, TPB>>>(pts, N, Nh, nb_head, out);
    if (N > Nh)
        vox_tail<<<TGRID, TPB>>>(pts, N, Nh, nb_head, nb_total, out);
    vox_emit<<<(MAXV + VB - 1) / VB, TPB>>>(pts, out);
}

// round 11
// speedup vs baseline: 1.0497x; 1.0497x over previous
#include <cuda_runtime.h>

// ---------------- problem constants ----------------
#define GX 1504
#define GY 1504
#define GZ 40
#define MAXV 150000
#define MAXP 10
#define N_MAX 2097152

#define SLOTBITS 22
#define SLOTS (1 << SLOTBITS)
#define SLOTMASK (SLOTS - 1)
#define BIG 0x40000000u                // phase-1 low32 offset; vids always < BIG

#define KBITS 19
#define KSLOTS (1 << KBITS)            // kept-voxel table: 150K keys / 512K slots
#define KMASK (KSLOTS - 1)

// output layout: voxels | coors | num_points | voxel_num  (all as float32)
#define VOX_OFF  0
#define COOR_OFF 7500000
#define NP_OFF   7950000
#define VN_OFF   8100000

#define TPB    256
#define TILE   256                           // 1 point per thread, tile == block
#define NB_MAX (N_MAX / TILE)                // 8192
#define M0     161792                        // 632*256; E[distinct]≈161.5K >> 150K
#define HGRID  (M0 / TPB)                    // 632 <= 740 co-resident (5 CTAs/SM)
#define TGRID  888                           // tail: 6 CTAs/SM co-resident
#define VB     128                           // emit voxels per block

// ---------------- device scratch ----------------
// Packed entry: high32 = flat+1 (key), low32 = BIG+(N-i) then vid.
// Persists across graph replays: stale (key|vid) dominated by BIG-offset atomicMax.
__device__ unsigned long long g_slot[SLOTS];  // 32 MB
__device__ int g_pflat[N_MAX];                // fallback-only per-point slot
__device__ unsigned long long g_tile[NB_MAX]; // fallback lookback state
__device__ int g_hcnt[HGRID];                 // head per-tile first counts
__device__ int g_sat;
__device__ int g_cnt[MAXV];
__device__ int g_idx[MAXV * MAXP];
__device__ unsigned long long g_kept[KSLOTS]; // (flat+1)<<32 | vid ; 0 = empty
__device__ unsigned g_bar_arrive;
__device__ unsigned g_bar_gen;

__device__ __forceinline__ unsigned hash_flat(int flat) {
    return ((unsigned)flat * 2654435761u) >> (32 - SLOTBITS);
}
__device__ __forceinline__ unsigned hash_kept(int flat) {
    return ((unsigned)flat * 0x9E3779B9u) >> (32 - KBITS);
}

// sense-reversing global barrier; caller guarantees all nb blocks co-resident.
// All threads fence so every phase's plain stores are L2-visible past the bar.
__device__ __forceinline__ void gbar(unsigned nb) {
    __threadfence();
    __syncthreads();
    if (threadIdx.x == 0) {
        unsigned gen = *((volatile unsigned*)&g_bar_gen);
        if (atomicAdd(&g_bar_arrive, 1u) == nb - 1u) {
            g_bar_arrive = 0u;
            __threadfence();
            atomicAdd(&g_bar_gen, 1u);
        } else {
            while (*((volatile unsigned*)&g_bar_gen) == gen) __nanosleep(40);
        }
        __threadfence();
    }
    __syncthreads();
}

// XLA-exact binning: fp32 sub, then multiply by compile-time fp32 reciprocal.
__device__ __forceinline__ int bin3(float x, float y, float z, int* flat) {
    const float rx = 1.0f / 0.1f;    // == 10.0f exactly
    const float rz = 1.0f / 0.15f;   // 0x40D55555
    int cx = (int)floorf(__fmul_rn(__fadd_rn(x, 75.2f), rx));
    int cy = (int)floorf(__fmul_rn(__fadd_rn(y, 75.2f), rx));
    int cz = (int)floorf(__fmul_rn(__fadd_rn(z, 2.0f), rz));
    if (cx < 0 || cx >= GX || cy < 0 || cy >= GY || cz < 0 || cz >= GZ) return 0;
    *flat = (cz * GY + cy) * GX + cx;
    return 1;
}

// head claim: probe-claim-record in one random line
__device__ __forceinline__ unsigned claim_record(int flat, unsigned v) {
    unsigned tag = (unsigned)(flat + 1);
    unsigned long long ent = ((unsigned long long)tag << 32) | v;
    unsigned h = hash_flat(flat);
    volatile unsigned long long* vs = (volatile unsigned long long*)g_slot;
    for (;;) {
        unsigned long long cur = vs[h];
        if ((unsigned)(cur >> 32) == tag) {        // warm replays: single read
            atomicMax(&g_slot[h], ent);
            break;
        }
        if (cur == 0ULL) {
            unsigned long long old = atomicCAS(&g_slot[h], 0ULL, ent);
            if (old == 0ULL) break;
            if ((unsigned)(old >> 32) == tag) { atomicMax(&g_slot[h], ent); break; }
        }
        h = (h + 1) & SLOTMASK;
    }
    return h;
}

// fallback claim (tail): head vids are FINAL -> never clobber lo32 < BIG entries.
__device__ __forceinline__ unsigned claim_fb(int flat, unsigned v) {
    unsigned tag = (unsigned)(flat + 1);
    unsigned long long ent = ((unsigned long long)tag << 32) | v;
    unsigned h = hash_flat(flat);
    volatile unsigned long long* vs = (volatile unsigned long long*)g_slot;
    for (;;) {
        unsigned long long cur = vs[h];
        if ((unsigned)(cur >> 32) == tag) {
            if ((unsigned)cur >= BIG) atomicMax(&g_slot[h], ent);
            break;
        }
        if (cur == 0ULL) {
            unsigned long long old = atomicCAS(&g_slot[h], 0ULL, ent);
            if (old == 0ULL) break;
            if ((unsigned)(old >> 32) == tag) {
                if ((unsigned)old >= BIG) atomicMax(&g_slot[h], ent);
                break;
            }
        }
        h = (h + 1) & SLOTMASK;
    }
    return h;
}

// shared-mem block scan of per-thread value; returns thread-exclusive, sets *tot
__device__ __forceinline__ int block_scan(int v, int* s_warp, int* tot) {
    int lane = threadIdx.x & 31, wid = threadIdx.x >> 5;
    int x = v;
#pragma unroll
    for (int o = 1; o < 32; o <<= 1) {
        int y = __shfl_up_sync(0xFFFFFFFFu, x, o);
        if (lane >= o) x += y;
    }
    if (lane == 31) s_warp[wid] = x;
    __syncthreads();
    if (wid == 0) {
        int w = (lane < 8) ? s_warp[lane] : 0;
#pragma unroll
        for (int o = 1; o < 8; o <<= 1) {
            int y = __shfl_up_sync(0xFFFFFFFFu, w, o);
            if (lane >= o) w += y;
        }
        if (lane < 8) s_warp[lane] = w;
    }
    __syncthreads();
    *tot = s_warp[7];
    return x - v + (wid > 0 ? s_warp[wid - 1] : 0);
}

// ---------------- kernel 1: head — lookback-free 3-phase pipeline --------------
__global__ void __launch_bounds__(TPB, 5) vox_head(const float* __restrict__ pts,
                                                   int N, int Nh, int nb_head,
                                                   float* __restrict__ out) {
    __shared__ int s_warp[8];
    __shared__ int s_pref[HGRID];              // 2.5 KB: replicated tile prefixes

    int tid = blockIdx.x * TPB + threadIdx.x;
    int gsz = gridDim.x * TPB;

    // phase 0: init + bin + claim (slot index stays in a register)
    for (int i = tid; i < NB_MAX; i += gsz) g_tile[i] = 0ULL;   // fallback state
    if (tid == 0) g_sat = 0;
    for (int i = tid; i < MAXV; i += gsz) g_cnt[i] = 0;

    int pf = -1;
    if (tid < Nh) {
        float x = pts[(size_t)tid * 5 + 0];
        float y = pts[(size_t)tid * 5 + 1];
        float z = pts[(size_t)tid * 5 + 2];
        int flat;
        if (bin3(x, y, z, &flat))
            pf = (int)claim_record(flat, BIG + (unsigned)(N - tid));
    }
    gbar(gridDim.x);

    // phase 1a: flag firsts (snapshot is stable: assigns happen after next gbar)
    unsigned long long ee = (pf >= 0) ? g_slot[pf] : 0ULL;
    int first = (pf >= 0 && (unsigned)ee == BIG + (unsigned)(N - tid)) ? 1 : 0;
    int btot;
    int texcl = block_scan(first, s_warp, &btot);
    if (threadIdx.x == 0) g_hcnt[blockIdx.x] = btot;
    gbar(gridDim.x);

    // phase 1b: every block scans all tile counts in smem (no serial chain)
    {
        int b0 = threadIdx.x * 3;               // 256*3 = 768 >= HGRID
        int c0 = 0, c1 = 0, c2 = 0;
        if (b0 + 0 < nb_head) c0 = g_hcnt[b0 + 0];
        if (b0 + 1 < nb_head) c1 = g_hcnt[b0 + 1];
        if (b0 + 2 < nb_head) c2 = g_hcnt[b0 + 2];
        int tot1b;
        __syncthreads();                        // s_warp reuse guard
        int cbase = block_scan(c0 + c1 + c2, s_warp, &tot1b);
        if (b0 + 0 < HGRID) s_pref[b0 + 0] = cbase;
        if (b0 + 1 < HGRID) s_pref[b0 + 1] = cbase + c0;
        if (b0 + 2 < HGRID) s_pref[b0 + 2] = cbase + c0 + c1;
        if (blockIdx.x == 0 && threadIdx.x == 0) {
            if (tot1b >= MAXV || Nh >= N) {     // saturated or head covers all
                g_sat = 1;
                out[VN_OFF] = (float)(tot1b < MAXV ? tot1b : MAXV);
            }
        }
        __syncthreads();
    }

    // phase 1c: assign vids, write coors + kept table
    int vid = s_pref[blockIdx.x] + texcl;
    if (first) {
        unsigned tag = (unsigned)(ee >> 32);
        int flat = (int)tag - 1;
        *((volatile unsigned long long*)&g_slot[pf]) =
            ((unsigned long long)tag << 32) | (unsigned)vid;   // unblocks spinners
        if (vid < MAXV) {
            int cx = flat % GX;
            int r = flat / GX;
            int cy = r % GY;
            int cz = r / GY;
            out[COOR_OFF + (size_t)vid * 3 + 0] = (float)cz;
            out[COOR_OFF + (size_t)vid * 3 + 1] = (float)cy;
            out[COOR_OFF + (size_t)vid * 3 + 2] = (float)cx;
            unsigned long long ent = ((unsigned long long)tag << 32) | (unsigned)vid;
            unsigned h2 = hash_kept(flat);
            volatile unsigned long long* vk = (volatile unsigned long long*)g_kept;
            for (;;) {
                unsigned long long cur = vk[h2];
                if ((unsigned)(cur >> 32) == tag) break;       // stale == idempotent
                if (cur == 0ULL) {
                    unsigned long long old = atomicCAS(&g_kept[h2], 0ULL, ent);
                    if (old == 0ULL || (unsigned)(old >> 32) == tag) break;
                }
                h2 = (h2 + 1) & KMASK;
            }
        }
    }
    __threadfence();
    __syncthreads();

    // phase 1d: slot points (non-firsts briefly spin for a concurrent assign)
    if (pf >= 0) {
        int v;
        if (first) {
            v = vid;
        } else {
            unsigned lo32 = (unsigned)*((volatile unsigned long long*)&g_slot[pf]);
            while (lo32 >= BIG) {
                __nanosleep(60);
                lo32 = (unsigned)*((volatile unsigned long long*)&g_slot[pf]);
            }
            v = (int)lo32;
        }
        if (v < MAXV) {
            int sl = atomicAdd(&g_cnt[v], 1);
            if (sl < MAXP) g_idx[v * MAXP + sl] = tid;
        }
    }
}

// ---------------- fallback fused tile (lookback version; adversarial path) -----
__device__ void fused_tile_fb(int tile, int pf, int N, int last_tile,
                              float* __restrict__ out) {
    __shared__ int s_warp[8];
    __shared__ int s_prefix;

    int i = tile * TILE + threadIdx.x;
    unsigned long long ee = (pf >= 0) ? g_slot[pf] : 0ULL;
    int first = (pf >= 0 && (unsigned)ee == BIG + (unsigned)(N - i)) ? 1 : 0;
    int total;
    int texcl = block_scan(first, s_warp, &total);

    if (threadIdx.x == 0)
        *((volatile unsigned long long*)&g_tile[tile]) = (1ULL << 32) | (unsigned)total;

    int lane = threadIdx.x & 31, wid = threadIdx.x >> 5;
    if (wid == 0) {
        int excl = 0;
        int look = tile - 1;
        while (look >= 0) {
            int idx = look - lane;
            unsigned long long p = (idx >= 0)
                ? *((volatile unsigned long long*)&g_tile[idx])
                : (2ULL << 32);
            int st = (int)(p >> 32);
            int val = (int)(p & 0xFFFFFFFFULL);
            unsigned bp = __ballot_sync(0xFFFFFFFFu, st == 2);
            unsigned bn = __ballot_sync(0xFFFFFFFFu, st == 0);
            if (bp) {
                int j = __ffs(bp) - 1;
                unsigned need = j ? ((1u << j) - 1u) : 0u;
                if ((bn & need) == 0) {
                    int c = (lane <= j) ? val : 0;
#pragma unroll
                    for (int o = 16; o > 0; o >>= 1) c += __shfl_down_sync(0xFFFFFFFFu, c, o);
                    excl += __shfl_sync(0xFFFFFFFFu, c, 0);
                    break;
                }
            } else if (bn == 0) {
                int c = val;
#pragma unroll
                for (int o = 16; o > 0; o >>= 1) c += __shfl_down_sync(0xFFFFFFFFu, c, o);
                excl += __shfl_sync(0xFFFFFFFFu, c, 0);
                look -= 32;
            }
        }
        if (lane == 0) {
            int tot = excl + total;
            *((volatile unsigned long long*)&g_tile[tile]) = (2ULL << 32) | (unsigned)tot;
            s_prefix = excl;
            if (tile == last_tile)
                out[VN_OFF] = (float)(tot < MAXV ? tot : MAXV);
        }
    }
    __syncthreads();

    int vid = s_prefix + texcl;
    if (first) {
        unsigned tag = (unsigned)(ee >> 32);
        int flat = (int)tag - 1;
        *((volatile unsigned long long*)&g_slot[pf]) =
            ((unsigned long long)tag << 32) | (unsigned)vid;
        if (vid < MAXV) {
            int cx = flat % GX;
            int r = flat / GX;
            int cy = r % GY;
            int cz = r / GY;
            out[COOR_OFF + (size_t)vid * 3 + 0] = (float)cz;
            out[COOR_OFF + (size_t)vid * 3 + 1] = (float)cy;
            out[COOR_OFF + (size_t)vid * 3 + 2] = (float)cx;
        }
    }
    __threadfence();
    __syncthreads();

    if (pf >= 0) {
        int v;
        if (first) {
            v = vid;
        } else {
            unsigned lo32 = (unsigned)*((volatile unsigned long long*)&g_slot[pf]);
            while (lo32 >= BIG) {
                __nanosleep(60);
                lo32 = (unsigned)*((volatile unsigned long long*)&g_slot[pf]);
            }
            v = (int)lo32;
        }
        if (v < MAXV) {
            int sl = atomicAdd(&g_cnt[v], 1);
            if (sl < MAXP) g_idx[v * MAXP + sl] = i;
        }
    }
}

// ---------------- kernel 2: tail — membership stream (+ in-kernel fallback) ----
#define TELEMS 4
__global__ void __launch_bounds__(TPB, 6) vox_tail(const float* __restrict__ pts,
                                                   int N, int Nh, int nb_head,
                                                   int nb_total,
                                                   float* __restrict__ out) {
    int sat = *((volatile int*)&g_sat);
    int tid = blockIdx.x * TPB + threadIdx.x;
    int gsz = gridDim.x * TPB;
    int lane = threadIdx.x & 31;
    int nwarp = gsz >> 5;
    int gw = tid >> 5;
    int nchunks = (N - Nh + 32 * TELEMS - 1) / (32 * TELEMS);

    for (int ch = gw; ch < nchunks; ch += nwarp) {
        int base = Nh + ch * (32 * TELEMS) + lane;
        float px[TELEMS], py[TELEMS], pz[TELEMS];
        int ok[TELEMS], flat[TELEMS];
#pragma unroll
        for (int k = 0; k < TELEMS; k++) {
            int i = base + k * 32;
            ok[k] = (i < N);
            if (ok[k]) {
                px[k] = __ldg(pts + (size_t)i * 5 + 0);
                py[k] = __ldg(pts + (size_t)i * 5 + 1);
                pz[k] = __ldg(pts + (size_t)i * 5 + 2);
            }
        }
#pragma unroll
        for (int k = 0; k < TELEMS; k++)
            if (ok[k]) ok[k] = bin3(px[k], py[k], pz[k], &flat[k]);

        if (sat) {
            unsigned h[TELEMS];
            unsigned long long e[TELEMS];
#pragma unroll
            for (int k = 0; k < TELEMS; k++) {
                if (ok[k]) {
                    h[k] = hash_kept(flat[k]);
                    e[k] = g_kept[h[k]];                  // batched first probes
                }
            }
#pragma unroll
            for (int k = 0; k < TELEMS; k++) {
                if (!ok[k]) continue;
                unsigned tag = (unsigned)(flat[k] + 1);
                unsigned hh = h[k];
                unsigned long long cur = e[k];
                for (;;) {
                    if (cur == 0ULL) break;               // voxel not kept
                    if ((unsigned)(cur >> 32) == tag) {
                        int v = (int)(unsigned)(cur & 0xFFFFFFFFULL);
                        int i = base + k * 32;
                        int sl = atomicAdd(&g_cnt[v], 1);
                        if (sl < MAXP) g_idx[v * MAXP + sl] = i;
                        break;
                    }
                    hh = (hh + 1) & KMASK;
                    cur = g_kept[hh];
                }
            }
        } else {
#pragma unroll
            for (int k = 0; k < TELEMS; k++) {
                int i = base + k * 32;
                if (i >= N) continue;
                if (!ok[k]) { g_pflat[i] = -1; continue; }
                g_pflat[i] = (int)claim_fb(flat[k], BIG + (unsigned)(N - i));
            }
        }
    }

    if (!sat) {
        // fallback: finish scan pipeline in-kernel. All TGRID blocks co-resident;
        // block-strided tiles -> lookback targets concurrent or done.
        gbar(gridDim.x);
        for (int t = nb_head + (int)blockIdx.x; t < nb_total; t += (int)gridDim.x) {
            int i = t * TILE + threadIdx.x;
            int pf = (i < N) ? g_pflat[i] : -1;
            fused_tile_fb(t, pf, N, nb_total - 1, out);
            __syncthreads();
        }
    }
}

// ---------------- kernel 3: emit — 2 threads/voxel, 25.6KB staging -------------
__global__ void __launch_bounds__(TPB) vox_emit(const float* __restrict__ pts,
                                                float* __restrict__ out) {
    __shared__ float srow[VB * 50];            // 25.6 KB -> 6 CTAs/SM
    int t = blockIdx.x;
    int vloc = threadIdx.x & (VB - 1);
    int half = threadIdx.x >> 7;               // 0: slots 0-4, 1: slots 5-9
    int vid = t * VB + vloc;
    if (vid < MAXV) {
        int c = g_cnt[vid];
        int m = c < MAXP ? c : MAXP;
        int a[MAXP];
        for (int k = 0; k < m; k++) a[k] = g_idx[vid * MAXP + k];
        for (int k = 1; k < m; k++) {          // restores deterministic point order
            int v = a[k];
            int j = k - 1;
            while (j >= 0 && a[j] > v) { a[j + 1] = a[j]; j--; }
            a[j + 1] = v;
        }
        float* row = srow + vloc * 50 + half * 25;
#pragma unroll
        for (int q = 0; q < 25; q++) row[q] = 0.0f;
        int k0 = half * 5;
        int k1 = m < k0 + 5 ? m : k0 + 5;
        for (int k = k0; k < k1; k++) {
            const float* p = pts + (size_t)a[k] * 5;
            float* d = row + (k - k0) * 5;
            d[0] = __ldg(p + 0);
            d[1] = __ldg(p + 1);
            d[2] = __ldg(p + 2);
            d[3] = __ldg(p + 3);
            d[4] = __ldg(p + 4);
        }
        if (half == 0) {
            out[NP_OFF + vid] = (float)m;
            if (m == 0) {                      // invalid slot -> coors = -1
                out[COOR_OFF + (size_t)vid * 3 + 0] = -1.0f;
                out[COOR_OFF + (size_t)vid * 3 + 1] = -1.0f;
                out[COOR_OFF + (size_t)vid * 3 + 2] = -1.0f;
            }
        }
    }
    __syncthreads();
    int rows = MAXV - t * VB;
    if (rows > VB) rows = VB;
    int nf4 = rows * 50 / 4;                   // 128->1600, 112->1400 (both exact)
    const float4* s4 = (const float4*)srow;
    float4* o4 = (float4*)(out + VOX_OFF + (size_t)t * VB * 50);
    for (int j = threadIdx.x; j < nf4; j += TPB) o4[j] = s4[j];
}

// ---------------- launch ----------------
extern "C" void kernel_launch(void* const* d_in, const int* in_sizes, int n_in,
                              void* d_out, int out_size) {
    const float* pts = (const float*)d_in[0];
    int N = in_sizes[0] / 5;
    if (N > N_MAX) N = N_MAX;
    float* out = (float*)d_out;

    int Nh = N < M0 ? N : M0;
    int nb_head = (Nh + TILE - 1) / TILE;      // <= 632
    int nb_total = (N + TILE - 1) / TILE;

    vox_head<<<HGRID, TPB>>>(pts, N, Nh, nb_head, out);
    if (N > Nh)
        vox_tail<<<TGRID, TPB>>>(pts, N, Nh, nb_head, nb_total, out);
    vox_emit<<<(MAXV + VB - 1) / VB, TPB>>>(pts, out);
}